// round 16
// baseline (speedup 1.0000x reference)
#include <cuda_runtime.h>
#include <cuda_fp16.h>
#include <cstdint>

#define SEQ   4096
#define BATCH 4
#define DIM   1024
#define RANK  64
#define NROW  (BATCH * SEQ)   // 16384
#define NTILE 32
#define TRI   528             // upper-tri tiles per batch
#define OFFD  496             // off-diagonal tiles per batch

// Scratch (__device__ globals per allocation rules)
__device__ __half g_pA16[NROW * RANK];  // p fp16, A-fragment layout (16KB/128-blk)
__device__ __half g_pB16[NROW * RANK];  // p fp16, B-fragment layout
__device__ float  g_sq[NROW];           // row sq norms (of fp16-rounded p)
__device__ __half g_pf16[DIM * RANK];   // proj fp16 B-fragments (16 chunks x 4096)

// ---------------- helpers ----------------
__device__ __forceinline__ uint32_t smem_u32(const void* p) {
    uint32_t a;
    asm("{ .reg .u64 t; cvta.to.shared.u64 t, %1; cvt.u32.u64 %0, t; }"
        : "=r"(a) : "l"(p));
    return a;
}
__device__ __forceinline__ void cpasync16(uint32_t s, const void* g) {
    asm volatile("cp.async.cg.shared.global [%0], [%1], 16;"
                 :: "r"(s), "l"(g) : "memory");
}
// pack two floats (f.x = even k, f.y = odd k) into f16x2 (lo = f.x)
__device__ __forceinline__ uint32_t h2pack(float2 f) {
    uint32_t r;
    asm("cvt.rn.f16x2.f32 %0, %1, %2;" : "=r"(r) : "f"(f.y), "f"(f.x));
    return r;
}
__device__ __forceinline__ void mma_f16(float* d, const uint32_t* a,
                                        uint32_t b0, uint32_t b1) {
    asm volatile(
        "mma.sync.aligned.m16n8k16.row.col.f32.f16.f16.f32 "
        "{%0,%1,%2,%3}, {%4,%5,%6,%7}, {%8,%9}, {%0,%1,%2,%3};"
        : "+f"(d[0]), "+f"(d[1]), "+f"(d[2]), "+f"(d[3])
        : "r"(a[0]), "r"(a[1]), "r"(a[2]), "r"(a[3]), "r"(b0), "r"(b1));
}

// ============================================================
// Kernel 0: proj -> fp16 B-fragment chunks (once).
// ============================================================
__global__ void __launch_bounds__(128) prep_proj_kernel(
    const float* __restrict__ proj) {
    int idx = blockIdx.x * 128 + threadIdx.x;   // 16384 float4s
    int k = idx >> 4, n4 = (idx & 15) << 2;
    float4 v = *(const float4*)(proj + (size_t)k * RANK + n4);
    int chunk = k >> 6, kk = k & 63;
    int kt = kk >> 4, cc = kk & 15, hf = cc & 1;
    __half* dst = g_pf16 + chunk * 4096;
    const float* vp = (const float*)&v;
#pragma unroll
    for (int j = 0; j < 4; j++) {
        int n = n4 + j;
        int ntb = n >> 3, gd = n & 7;
        dst[((ntb * 4 + kt) * 32 + gd * 4 + ((cc & 7) >> 1)) * 4 +
            ((cc >= 8) ? 2 : 0) + hf] = __float2half_rn(vp[j]);
    }
}

// ============================================================
// Kernel 1: proj GEMM (fp16 m16n8k16). chunk = blk0 + blockIdx.x
// (64 rows each). K=1024 in EIGHT iterations of 128 (halved serial
// chain), 2-stage double buffer (100KB -> 2 CTA/SM).
// ============================================================
#define XST 132
#define XBUF (64 * XST)                 // 8448 floats (33792 B)
#define PBUF16 8192                     // halves per 128-K chunk (16384 B)
#define STAGE_B (XBUF * 4 + PBUF16 * 2) // 50176 B
#define PROJ_SMEM (2 * STAGE_B)         // 100352 B -> 2 CTA/SM

__global__ void __launch_bounds__(256, 2) proj_mma_kernel(
    const float* __restrict__ x, int blk0) {
    extern __shared__ __align__(16) char smc[];
    __shared__ float s_part[2][64];

    const int tid = threadIdx.x, wid = tid >> 5, lane = tid & 31;
    const int gid = lane >> 2, tig = lane & 3;
    const int wm = wid & 3, wn = wid >> 2;
    const int cid = blk0 + blockIdx.x;
    const int rowbase = cid * 64;
    const uint32_t sbase = smem_u32(smc);

    float acc[4][4];
#pragma unroll
    for (int i = 0; i < 4; i++)
#pragma unroll
        for (int j = 0; j < 4; j++) acc[i][j] = 0.f;

    auto load_stage = [&](int it, int buf) {
        const uint32_t sb = sbase + (uint32_t)(buf * STAGE_B);
        const float* src = x + (size_t)rowbase * DIM + it * 128;
        // x: 64 rows x 128 cols fp32 (2048 float4s, 8 per thread)
#pragma unroll
        for (int l = 0; l < 8; l++) {
            int idx = tid + l * 256;
            int r = idx >> 5, c4 = (idx & 31) << 2;
            cpasync16(sb + (uint32_t)(r * XST + c4) * 4,
                      src + (size_t)r * DIM + c4);
        }
        // pf: two consecutive 4096-half fragment chunks = 16KB
        const float4* pf = (const float4*)(g_pf16 + it * PBUF16);
#pragma unroll
        for (int l = 0; l < 4; l++) {
            int idx = tid + l * 256;
            cpasync16(sb + (uint32_t)(XBUF * 4 + idx * 16), pf + idx);
        }
        asm volatile("cp.async.commit_group;" ::: "memory");
    };

    load_stage(0, 0);
    load_stage(1, 1);

    for (int it = 0; it < 8; ++it) {
        if (it < 7) asm volatile("cp.async.wait_group 1;" ::: "memory");
        else        asm volatile("cp.async.wait_group 0;" ::: "memory");
        __syncthreads();

        const int buf = it & 1;
        const float* xb = (const float*)(smc + buf * STAGE_B);
        const uint32_t* pb = (const uint32_t*)(xb + XBUF);
        const int r0 = wm * 16 + gid;
#pragma unroll
        for (int kt = 0; kt < 8; kt++) {
            const int c = kt * 16 + 2 * tig;
            uint32_t a[4];
            a[0] = h2pack(*(const float2*)&xb[r0 * XST + c]);
            a[1] = h2pack(*(const float2*)&xb[(r0 + 8) * XST + c]);
            a[2] = h2pack(*(const float2*)&xb[r0 * XST + c + 8]);
            a[3] = h2pack(*(const float2*)&xb[(r0 + 8) * XST + c + 8]);
            const uint32_t* pbc = pb + (kt >> 2) * 2048;
            const int kq = kt & 3;
#pragma unroll
            for (int nt = 0; nt < 4; nt++) {
                const int ng = wn * 4 + nt;
                const uint2 bb =
                    *(const uint2*)(pbc + ((ng * 4 + kq) * 32 + lane) * 2);
                mma_f16(acc[nt], a, bb.x, bb.y);
            }
        }
        __syncthreads();   // all warps done with buf before refill
        if (it + 2 < 8) load_stage(it + 2, buf);
    }

    // ---- epilogue: round to fp16, sq from rounded values, scatter ----
    __half hv[4][4];
    float sq1 = 0.f, sq2 = 0.f;
#pragma unroll
    for (int nt = 0; nt < 4; nt++) {
#pragma unroll
        for (int j = 0; j < 4; j++) {
            hv[nt][j] = __float2half_rn(acc[nt][j]);
            acc[nt][j] = __half2float(hv[nt][j]);
        }
        sq1 += acc[nt][0] * acc[nt][0] + acc[nt][1] * acc[nt][1];
        sq2 += acc[nt][2] * acc[nt][2] + acc[nt][3] * acc[nt][3];
    }
    sq1 += __shfl_xor_sync(0xffffffffu, sq1, 1);
    sq1 += __shfl_xor_sync(0xffffffffu, sq1, 2);
    sq2 += __shfl_xor_sync(0xffffffffu, sq2, 1);
    sq2 += __shfl_xor_sync(0xffffffffu, sq2, 2);

    const int r1 = wm * 16 + gid, r2 = r1 + 8;
    if (tig == 0) {
        s_part[wn][r1] = sq1;
        s_part[wn][r2] = sq2;
    }
    __syncthreads();
    if (tid < 64) g_sq[rowbase + tid] = s_part[0][tid] + s_part[1][tid];

    const int bb = cid >> 1;
    const int half = (cid & 1) * 64;
    __half* gA = g_pA16 + (size_t)bb * 8192;
    __half* gB = g_pB16 + (size_t)bb * 8192;
#pragma unroll
    for (int nt = 0; nt < 4; nt++) {
#pragma unroll
        for (int jj = 0; jj < 4; jj++) {
            const int lr = half + ((jj >= 2) ? r2 : r1);
            const int c = wn * 32 + nt * 8 + 2 * tig + (jj & 1);
            const __half v = hv[nt][jj];
            const int cc = c & 15, kt = c >> 4, hf = cc & 1;
            {   // A-fragment (m16n8k16 row-major)
                int mt = lr >> 4, r = lr & 15;
                int q = ((r >> 3) & 1) | ((cc >= 8) ? 2 : 0);
                int ln = (r & 7) * 4 + ((cc & 7) >> 1);
                gA[((mt * 4 + kt) * 32 + ln) * 8 + q * 2 + hf] = v;
            }
            {   // B-fragment (n8k16 col-major)
                int ntb = lr >> 3, gd = lr & 7;
                int q = (cc >= 8) ? 1 : 0;
                int ln = gd * 4 + ((cc & 7) >> 1);
                gB[((ntb * 4 + kt) * 32 + ln) * 4 + q * 2 + hf] = v;
            }
        }
    }
}

// ============================================================
// Kernel 2: dist fp16, symmetric, 256 threads; batch = bz0+blockIdx.z.
// ============================================================
#define DIST_SMEM (8192 * 4)   // 32 KB (two 16KB fp16 operand tiles)

__global__ void __launch_bounds__(256, 2) dist_mma_kernel(
    float* __restrict__ out, int bz0) {
    extern __shared__ __align__(16) uint32_t sm32[];
    __shared__ float s_sqA[128], s_sqB[128];

    const int tid = threadIdx.x, wid = tid >> 5, lane = tid & 31;
    const int gid = lane >> 2, tig = lane & 3;
    const int bz = bz0 + blockIdx.z;

    const int t = blockIdx.x;
    int i, j;
    if (t < OFFD) {
        j = (int)((1.f + sqrtf(1.f + 8.f * (float)t)) * 0.5f);
        while (j * (j - 1) / 2 > t) j--;
        while ((j + 1) * j / 2 <= t) j++;
        i = t - j * (j - 1) / 2;
    } else {
        i = j = t - OFFD;
    }

    const int ablk = bz * NTILE + i, bblk = bz * NTILE + j;
    const uint32_t sbase = smem_u32(sm32);

    const float4* gA = (const float4*)(g_pA16 + (size_t)ablk * 8192);
    const float4* gB = (const float4*)(g_pB16 + (size_t)bblk * 8192);
#pragma unroll
    for (int l = 0; l < 4; l++) {
        int idx = tid + l * 256;
        cpasync16(sbase + (uint32_t)idx * 16, gA + idx);
        cpasync16(sbase + 16384u + (uint32_t)idx * 16, gB + idx);
    }
    asm volatile("cp.async.commit_group;" ::: "memory");
    if (tid < 128) s_sqA[tid] = g_sq[ablk * 128 + tid];
    else           s_sqB[tid - 128] = g_sq[bblk * 128 + (tid - 128)];
    asm volatile("cp.async.wait_group 0;" ::: "memory");
    __syncthreads();

    const int wm = wid & 1, wn = wid >> 1;
    const uint32_t* As = sm32;
    const uint32_t* Bs = sm32 + 4096;

    float acc[4][4][4];
#pragma unroll
    for (int a = 0; a < 4; a++)
#pragma unroll
        for (int b = 0; b < 4; b++)
#pragma unroll
            for (int c = 0; c < 4; c++) acc[a][b][c] = 0.f;

#pragma unroll
    for (int kt = 0; kt < 4; kt++) {
        uint4 a[4];
        uint2 b[4];
#pragma unroll
        for (int mt = 0; mt < 4; mt++)
            a[mt] = *(const uint4*)(As + ((wm * 4 + mt) * 4 + kt) * 128 + lane * 4);
#pragma unroll
        for (int nt = 0; nt < 4; nt++)
            b[nt] = *(const uint2*)(Bs + ((wn * 4 + nt) * 4 + kt) * 64 + lane * 2);
#pragma unroll
        for (int mt = 0; mt < 4; mt++)
#pragma unroll
            for (int nt = 0; nt < 4; nt++)
                mma_f16(acc[mt][nt], (const uint32_t*)&a[mt], b[nt].x, b[nt].y);
    }

#pragma unroll
    for (int mt = 0; mt < 4; mt++) {
        const int rl1 = wm * 64 + mt * 16 + gid, rl2 = rl1 + 8;
        const float sA1 = s_sqA[rl1], sA2 = s_sqA[rl2];
#pragma unroll
        for (int nt = 0; nt < 4; nt++) {
            const int cl = wn * 32 + nt * 8 + 2 * tig;
            const float sB0 = s_sqB[cl], sB1 = s_sqB[cl + 1];
            acc[mt][nt][0] = fmaxf(sA1 + sB0 - 2.f * acc[mt][nt][0], 0.f);
            acc[mt][nt][1] = fmaxf(sA1 + sB1 - 2.f * acc[mt][nt][1], 0.f);
            acc[mt][nt][2] = fmaxf(sA2 + sB0 - 2.f * acc[mt][nt][2], 0.f);
            acc[mt][nt][3] = fmaxf(sA2 + sB1 - 2.f * acc[mt][nt][3], 0.f);
        }
    }

#pragma unroll
    for (int mt = 0; mt < 4; mt++) {
        const int rl1 = wm * 64 + mt * 16 + gid;
        float* o1 = out + ((size_t)bz * SEQ + i * 128 + rl1) * SEQ + j * 128;
        float* o2 = o1 + (size_t)8 * SEQ;
#pragma unroll
        for (int nt = 0; nt < 4; nt++) {
            const int cl = wn * 32 + nt * 8 + 2 * tig;
            __stcs((float2*)(o1 + cl), make_float2(acc[mt][nt][0], acc[mt][nt][1]));
            __stcs((float2*)(o2 + cl), make_float2(acc[mt][nt][2], acc[mt][nt][3]));
        }
    }

    if (i != j) {
        float* tb = out + ((size_t)bz * SEQ + j * 128) * SEQ + i * 128;
#pragma unroll
        for (int nt = 0; nt < 4; nt++) {
            const int cl = wn * 32 + nt * 8 + 2 * tig;
            float* c0 = tb + (size_t)cl * SEQ;
            float* c1 = c0 + SEQ;
#pragma unroll
            for (int mt = 0; mt < 4; mt++) {
                const int rl1 = wm * 64 + mt * 16 + gid;
                __stcs(c0 + rl1,     acc[mt][nt][0]);
                __stcs(c1 + rl1,     acc[mt][nt][1]);
                __stcs(c0 + rl1 + 8, acc[mt][nt][2]);
                __stcs(c1 + rl1 + 8, acc[mt][nt][3]);
            }
        }
    }
}

// ============================================================
// Launch: forked-stream graph (proven in R15).
//   s0: prep -> fork -> proj(batches 1-3) -> dist(batches 1-3) -> join
//   sB:          fork -> proj(batch 0)    -> dist(batch 0)     -> join
// ============================================================
extern "C" void kernel_launch(void* const* d_in, const int* in_sizes, int n_in,
                              void* d_out, int out_size) {
    const float* x = (const float*)d_in[0];
    const float* proj = (const float*)d_in[1];
    float* out = (float*)d_out;

    static cudaStream_t sB = nullptr;
    static cudaEvent_t evFork = nullptr, evJoin = nullptr;
    if (sB == nullptr) {
        cudaStreamCreateWithFlags(&sB, cudaStreamNonBlocking);
        cudaEventCreateWithFlags(&evFork, cudaEventDisableTiming);
        cudaEventCreateWithFlags(&evJoin, cudaEventDisableTiming);
    }

    cudaFuncSetAttribute(proj_mma_kernel,
                         cudaFuncAttributeMaxDynamicSharedMemorySize, PROJ_SMEM);
    cudaFuncSetAttribute(dist_mma_kernel,
                         cudaFuncAttributeMaxDynamicSharedMemorySize, DIST_SMEM);

    prep_proj_kernel<<<128, 128>>>(proj);

    cudaEventRecord(evFork, 0);
    cudaStreamWaitEvent(sB, evFork, 0);

    // branch B: batch 0 (64 proj chunks -> 528 dist tiles)
    proj_mma_kernel<<<64, 256, PROJ_SMEM, sB>>>(x, 0);
    dist_mma_kernel<<<dim3(TRI, 1, 1), 256, DIST_SMEM, sB>>>(out, 0);

    // branch A: batches 1-3 (192 proj chunks -> 1584 dist tiles)
    proj_mma_kernel<<<192, 256, PROJ_SMEM, 0>>>(x, 64);
    dist_mma_kernel<<<dim3(TRI, 1, 3), 256, DIST_SMEM, 0>>>(out, 1);

    cudaEventRecord(evJoin, sB);
    cudaStreamWaitEvent(0, evJoin, 0);
}